// round 4
// baseline (speedup 1.0000x reference)
#include <cuda_runtime.h>
#include <cfloat>

#define NN 100000
#define CC 200
#define EE 400000
#define GG 512
#define HH 4
#define DD 50
#define EN (EE + NN)

// ---------------- scratch (device globals; no runtime allocation) ----------
__device__ float g_h[(size_t)NN * CC];     // post-LN+ELU features
__device__ float g_xh[(size_t)NN * CC];    // h @ W_gat
__device__ float g_asrc[NN * HH];
__device__ float g_adst[NN * HH];
__device__ unsigned g_mu[NN * HH];         // segment max per dst,head (encoded)
__device__ float g_z[NN * HH];             // segment sum of exp
__device__ float g_e[(size_t)EN * HH];     // per-edge exp(alpha - m)
__device__ float g_gsum[GG], g_gsq[GG], g_gcnt[GG], g_gmean[GG], g_ginv[GG];
__device__ float g_srel[NN], g_sbase[NN], g_agg[NN], g_es[NN], g_scale[NN];
__device__ unsigned g_gmu[GG];
__device__ float g_gz[GG];

// ---------------- helpers ---------------------------------------------------
// order-preserving float -> uint key (radix-sort flip); NaN-free inputs here
__device__ __forceinline__ unsigned fkey(float f) {
    unsigned b = __float_as_uint(f);
    return b ^ ((unsigned)((int)b >> 31) | 0x80000000u);
}
__device__ __forceinline__ float funkey(unsigned u) {
    unsigned b = (u & 0x80000000u) ? (u ^ 0x80000000u) : ~u;
    return __uint_as_float(b);
}

__device__ __forceinline__ float warpSum(float v) {
#pragma unroll
    for (int o = 16; o; o >>= 1) v += __shfl_down_sync(0xffffffffu, v, o);
    return v;
}

__device__ __forceinline__ float lrelu(float a) { return a > 0.f ? a : 0.2f * a; }

// ---------------- kernels ---------------------------------------------------

// init: out=bias broadcast, outg=0, segment-op identities
__global__ void k_init(float* __restrict__ out, float* __restrict__ outg,
                       const float* __restrict__ bias) {
    int i = blockIdx.x * blockDim.x + threadIdx.x;
    if (i < NN * CC) out[i] = bias[i % CC];
    if (i < NN * HH) { g_mu[i] = 0u; g_z[i] = 0.f; }
    if (i < NN) g_agg[i] = 0.f;
    if (i < GG) {
        g_gsum[i] = 0.f; g_gsq[i] = 0.f; g_gcnt[i] = 0.f;
        g_gmu[i] = 0u; g_gz[i] = 0.f;
    }
    if (i < GG * CC) outg[i] = 0.f;
}

// per-node sums for graph-mode LayerNorm (one warp per node)
__global__ void k_ln_stats(const float* __restrict__ x,
                           const int* __restrict__ batch) {
    int gw = (blockIdx.x * blockDim.x + threadIdx.x) >> 5;
    int lane = threadIdx.x & 31;
    if (gw >= NN) return;
    const float* row = &x[(size_t)gw * CC];
    float s = 0.f, s2 = 0.f;
#pragma unroll
    for (int t = 0; t < 7; t++) {
        int c = lane + t * 32;
        if (c < CC) { float v = row[c]; s += v; s2 += v * v; }
    }
    s = warpSum(s); s2 = warpSum(s2);
    if (lane == 0) {
        int b = batch[gw];
        atomicAdd(&g_gsum[b], s);
        atomicAdd(&g_gsq[b], s2);
        atomicAdd(&g_gcnt[b], 1.f);
    }
}

__global__ void k_ln_final() {
    int i = blockIdx.x * blockDim.x + threadIdx.x;
    if (i >= GG) return;
    float cnt = g_gcnt[i];
    float mean = 0.f, inv = 0.f;
    if (cnt > 0.f) {
        float denom = cnt * (float)CC;
        mean = g_gsum[i] / denom;
        float var = g_gsq[i] / denom - mean * mean;
        inv = rsqrtf(var + 1e-5f);
    }
    g_gmean[i] = mean;
    g_ginv[i] = inv;
}

// h = elu(LN(x))
__global__ void k_h(const float* __restrict__ x, const int* __restrict__ batch,
                    const float* __restrict__ lnw, const float* __restrict__ lnb) {
    int i = blockIdx.x * blockDim.x + threadIdx.x;
    if (i >= NN * CC) return;
    int n = i / CC, c = i - n * CC;
    int b = batch[n];
    float v = (x[i] - g_gmean[b]) * g_ginv[b] * lnw[c] + lnb[c];
    g_h[i] = v > 0.f ? v : expm1f(v);
}

// xh = g_h @ W  (fp32; BM=128, BN=64, BK=8; 256 thr, 8x4 per thread; scalar LDG)
__global__ void __launch_bounds__(256) k_gemm(const float* __restrict__ W) {
    __shared__ float As[8][132];   // transposed: As[k][m], padded
    __shared__ float Bs[8][64];
    const int bm = blockIdx.x * 128;
    const int bn = blockIdx.y * 64;
    const int tid = threadIdx.x;
    const int tx = tid & 15;       // col group of 4
    const int ty = tid >> 4;       // row group of 8

    float acc[8][4];
#pragma unroll
    for (int i = 0; i < 8; i++)
#pragma unroll
        for (int j = 0; j < 4; j++) acc[i][j] = 0.f;

    const int arow = tid >> 1;           // 0..127
    const int ak0 = (tid & 1) * 4;       // 0 or 4
    const int bk = tid >> 5;             // 0..7
    const int bc0 = (tid & 31) * 2;      // 0..62

    for (int k0 = 0; k0 < CC; k0 += 8) {
        int grow = bm + arow;
#pragma unroll
        for (int q = 0; q < 4; q++) {
            float v = 0.f;
            if (grow < NN) v = g_h[(size_t)grow * CC + k0 + ak0 + q];
            As[ak0 + q][arow] = v;
        }
#pragma unroll
        for (int q = 0; q < 2; q++) {
            int gcol = bn + bc0 + q;
            float v = 0.f;
            if (gcol < CC) v = W[(size_t)(k0 + bk) * CC + gcol];
            Bs[bk][bc0 + q] = v;
        }
        __syncthreads();

#pragma unroll
        for (int k = 0; k < 8; k++) {
            float a[8], b[4];
#pragma unroll
            for (int i = 0; i < 8; i++) a[i] = As[k][ty * 8 + i];
#pragma unroll
            for (int j = 0; j < 4; j++) b[j] = Bs[k][tx * 4 + j];
#pragma unroll
            for (int i = 0; i < 8; i++)
#pragma unroll
                for (int j = 0; j < 4; j++) acc[i][j] = fmaf(a[i], b[j], acc[i][j]);
        }
        __syncthreads();
    }

#pragma unroll
    for (int i = 0; i < 8; i++) {
        int r = bm + ty * 8 + i;
        if (r >= NN) break;
#pragma unroll
        for (int j = 0; j < 4; j++) {
            int c = bn + tx * 4 + j;
            if (c < CC) g_xh[(size_t)r * CC + c] = acc[i][j];
        }
    }
}

// per-node attention logits a_src, a_dst (one warp per node)
__global__ void k_att(const float* __restrict__ att_s, const float* __restrict__ att_d) {
    __shared__ float s_as[CC], s_ad[CC];
    for (int i = threadIdx.x; i < CC; i += blockDim.x) {
        s_as[i] = att_s[i];
        s_ad[i] = att_d[i];
    }
    __syncthreads();
    int gw = (blockIdx.x * blockDim.x + threadIdx.x) >> 5;
    int lane = threadIdx.x & 31;
    if (gw >= NN) return;
    const float* row = &g_xh[(size_t)gw * CC];
#pragma unroll
    for (int hh = 0; hh < HH; hh++) {
        float ss = 0.f, sd = 0.f;
#pragma unroll
        for (int t = 0; t < 2; t++) {
            int d = lane + t * 32;
            if (d < DD) {
                float v = row[hh * DD + d];
                ss += v * s_as[hh * DD + d];
                sd += v * s_ad[hh * DD + d];
            }
        }
        ss = warpSum(ss); sd = warpSum(sd);
        if (lane == 0) {
            g_asrc[gw * HH + hh] = ss;
            g_adst[gw * HH + hh] = sd;
        }
    }
}

__device__ __forceinline__ void edge_ends(const int* ei, int i, int& src, int& dst) {
    if (i < EE) { src = ei[i]; dst = ei[EE + i]; }
    else        { src = i - EE; dst = src; }
}

__global__ void k_edge_max(const int* __restrict__ ei) {
    int i = blockIdx.x * blockDim.x + threadIdx.x;
    if (i >= EN) return;
    int src, dst;
    edge_ends(ei, i, src, dst);
#pragma unroll
    for (int hh = 0; hh < HH; hh++) {
        float a = lrelu(g_asrc[src * HH + hh] + g_adst[dst * HH + hh]);
        atomicMax(&g_mu[dst * HH + hh], fkey(a));
    }
}

__global__ void k_edge_exp(const int* __restrict__ ei) {
    int i = blockIdx.x * blockDim.x + threadIdx.x;
    if (i >= EN) return;
    int src, dst;
    edge_ends(ei, i, src, dst);
#pragma unroll
    for (int hh = 0; hh < HH; hh++) {
        float a = lrelu(g_asrc[src * HH + hh] + g_adst[dst * HH + hh]);
        float m = funkey(g_mu[dst * HH + hh]);
        float e = expf(a - m);
        g_e[(size_t)i * HH + hh] = e;
        atomicAdd(&g_z[dst * HH + hh], e);
    }
}

// out[dst] += xh[src] * att   (one warp per edge; out pre-initialized to bias)
__global__ void k_edge_scatter(const int* __restrict__ ei, float* __restrict__ out) {
    int gw = (blockIdx.x * blockDim.x + threadIdx.x) >> 5;
    int lane = threadIdx.x & 31;
    if (gw >= EN) return;
    int src, dst;
    edge_ends(ei, gw, src, dst);
    float att[HH];
#pragma unroll
    for (int hh = 0; hh < HH; hh++)
        att[hh] = g_e[(size_t)gw * HH + hh] / (g_z[dst * HH + hh] + 1e-16f);
    const float* xr = &g_xh[(size_t)src * CC];
    float* orow = &out[(size_t)dst * CC];
#pragma unroll
    for (int t = 0; t < 7; t++) {
        int c = lane + t * 32;
        if (c < CC) {
            int hh = c / DD;
            atomicAdd(&orow[c], xr[c] * att[hh]);
        }
    }
}

// per-node projections: srel = out . w_rel ; sbase = out . w_root + b_rel
__global__ void k_score_node(const float* __restrict__ out, const float* __restrict__ w_rel,
                             const float* __restrict__ w_root, const float* __restrict__ b_rel) {
    int gw = (blockIdx.x * blockDim.x + threadIdx.x) >> 5;
    int lane = threadIdx.x & 31;
    if (gw >= NN) return;
    const float* r = &out[(size_t)gw * CC];
    float sr = 0.f, sb = 0.f;
#pragma unroll
    for (int t = 0; t < 7; t++) {
        int c = lane + t * 32;
        if (c < CC) {
            float v = r[c];
            sr += v * w_rel[c];
            sb += v * w_root[c];
        }
    }
    sr = warpSum(sr); sb = warpSum(sb);
    if (lane == 0) {
        g_srel[gw] = sr;
        g_sbase[gw] = sb + b_rel[0];
    }
}

// agg[dst] += srel[src] over ORIGINAL edges only
__global__ void k_edge_rel(const int* __restrict__ ei) {
    int i = blockIdx.x * blockDim.x + threadIdx.x;
    if (i >= EE) return;
    atomicAdd(&g_agg[ei[EE + i]], g_srel[ei[i]]);
}

__global__ void k_score_max(const int* __restrict__ batch) {
    int i = blockIdx.x * blockDim.x + threadIdx.x;
    if (i >= NN) return;
    float s = g_agg[i] + g_sbase[i];
    g_sbase[i] = s;
    atomicMax(&g_gmu[batch[i]], fkey(s));
}

__global__ void k_score_exp(const int* __restrict__ batch) {
    int i = blockIdx.x * blockDim.x + threadIdx.x;
    if (i >= NN) return;
    int b = batch[i];
    float es = expf(g_sbase[i] - funkey(g_gmu[b]));
    g_es[i] = es;
    atomicAdd(&g_gz[b], es);
}

__global__ void k_scale(const int* __restrict__ batch) {
    int i = blockIdx.x * blockDim.x + threadIdx.x;
    if (i >= NN) return;
    g_scale[i] = g_es[i] / g_gz[batch[i]];
}

// xp = out*scale (in place) ; outg[batch] += xp
__global__ void k_finalize(float* __restrict__ out, float* __restrict__ outg,
                           const int* __restrict__ batch) {
    int i = blockIdx.x * blockDim.x + threadIdx.x;
    if (i >= NN * CC) return;
    int n = i / CC, c = i - n * CC;
    float v = out[i] * g_scale[n];
    out[i] = v;
    atomicAdd(&outg[(size_t)batch[n] * CC + c], v);
}

// ---------------- launch ----------------------------------------------------
extern "C" void kernel_launch(void* const* d_in, const int* in_sizes, int n_in,
                              void* d_out, int out_size) {
    const float* x = (const float*)d_in[0];
    const int* ei = (const int*)d_in[1];
    const int* batch = (const int*)d_in[2];
    const float* ln_w = (const float*)d_in[3];
    const float* ln_b = (const float*)d_in[4];
    const float* W_gat = (const float*)d_in[5];
    const float* att_s = (const float*)d_in[6];
    const float* att_d = (const float*)d_in[7];
    const float* bias = (const float*)d_in[8];
    const float* w_rel = (const float*)d_in[9];
    const float* b_rel = (const float*)d_in[10];
    const float* w_root = (const float*)d_in[11];

    float* out = (float*)d_out;                 // xp region [N, C]
    float* outg = out + (size_t)NN * CC;        // g region  [G, C]

    const int T = 256;
    const int blocksNC = (NN * CC + T - 1) / T;       // 78125
    const int warpNodeBlocks = (NN + 7) / 8;          // 12500 (8 warps/block)
    const int edgeBlocks = (EN + T - 1) / T;          // 1954
    const int edgeWarpBlocks = (EN + 7) / 8;          // 62500
    const int nodeBlocks = (NN + T - 1) / T;          // 391
    (void)in_sizes; (void)n_in; (void)out_size;

    k_init<<<blocksNC, T>>>(out, outg, bias);
    k_ln_stats<<<warpNodeBlocks, T>>>(x, batch);
    k_ln_final<<<(GG + T - 1) / T, T>>>();
    k_h<<<blocksNC, T>>>(x, batch, ln_w, ln_b);

    dim3 gemmGrid((NN + 127) / 128, 4);
    k_gemm<<<gemmGrid, 256>>>(W_gat);

    k_att<<<warpNodeBlocks, T>>>(att_s, att_d);
    k_edge_max<<<edgeBlocks, T>>>(ei);
    k_edge_exp<<<edgeBlocks, T>>>(ei);
    k_edge_scatter<<<edgeWarpBlocks, T>>>(ei, out);

    k_score_node<<<warpNodeBlocks, T>>>(out, w_rel, w_root, b_rel);
    k_edge_rel<<<(EE + T - 1) / T, T>>>(ei);
    k_score_max<<<nodeBlocks, T>>>(batch);
    k_score_exp<<<nodeBlocks, T>>>(batch);
    k_scale<<<nodeBlocks, T>>>(batch);
    k_finalize<<<blocksNC, T>>>(out, outg, batch);
}

// round 5
// speedup vs baseline: 1.2571x; 1.2571x over previous
#include <cuda_runtime.h>
#include <cfloat>

#define NN 100000
#define CC 200
#define EE 400000
#define GG 512
#define HH 4
#define DD 50
#define EN (EE + NN)
#define NC4 (NN * (CC / 4))   // 5,000,000 float4 groups in [N,C]

// ---------------- scratch (device globals; no runtime allocation) ----------
__device__ __align__(16) float g_h[(size_t)NN * CC];     // post-LN+ELU features
__device__ __align__(16) float g_xh[(size_t)NN * CC];    // h @ W_gat
__device__ __align__(16) float g_asrc[NN * HH];
__device__ __align__(16) float g_adst[NN * HH];
__device__ __align__(16) unsigned g_mu[NN * HH];         // segment max (encoded)
__device__ __align__(16) float g_z[NN * HH];             // segment sum of exp
__device__ __align__(16) float g_e[(size_t)EN * HH];     // per-edge exp(alpha-m)
__device__ float g_gsum[GG], g_gsq[GG], g_gcnt[GG], g_gmean[GG], g_ginv[GG];
__device__ float g_srel[NN], g_sbase[NN], g_agg[NN], g_es[NN], g_scale[NN];
__device__ unsigned g_gmu[GG];
__device__ float g_gz[GG];

// ---------------- helpers ---------------------------------------------------
__device__ __forceinline__ unsigned fkey(float f) {
    unsigned b = __float_as_uint(f);
    return b ^ ((unsigned)((int)b >> 31) | 0x80000000u);
}
__device__ __forceinline__ float funkey(unsigned u) {
    unsigned b = (u & 0x80000000u) ? (u ^ 0x80000000u) : ~u;
    return __uint_as_float(b);
}
__device__ __forceinline__ float warpSum(float v) {
#pragma unroll
    for (int o = 16; o; o >>= 1) v += __shfl_down_sync(0xffffffffu, v, o);
    return v;
}
__device__ __forceinline__ float lrelu(float a) { return a > 0.f ? a : 0.2f * a; }

// packed f32x2 FMA (PTX-only dual-issue fp32)
__device__ __forceinline__ unsigned long long pack2(float x, float y) {
    unsigned long long r;
    asm("mov.b64 %0, {%1, %2};" : "=l"(r)
        : "r"(__float_as_uint(x)), "r"(__float_as_uint(y)));
    return r;
}
__device__ __forceinline__ void fma2(unsigned long long& d, unsigned long long a,
                                     unsigned long long b) {
    asm("fma.rn.f32x2 %0, %1, %2, %0;" : "+l"(d) : "l"(a), "l"(b));
}
__device__ __forceinline__ float2 unpack2(unsigned long long v) {
    unsigned lo, hi;
    asm("mov.b64 {%0, %1}, %2;" : "=r"(lo), "=r"(hi) : "l"(v));
    return make_float2(__uint_as_float(lo), __uint_as_float(hi));
}

// vectorized fp32 reduction (PTX 8.1+, sm_90+)
__device__ __forceinline__ void red_add_v4(float* addr, float a, float b, float c, float d) {
    asm volatile("red.global.add.v4.f32 [%0], {%1, %2, %3, %4};"
                 :: "l"(addr), "f"(a), "f"(b), "f"(c), "f"(d) : "memory");
}

// ---------------- kernels ---------------------------------------------------

__global__ void k_init(float* __restrict__ out, float* __restrict__ outg,
                       const float* __restrict__ bias) {
    int i = blockIdx.x * blockDim.x + threadIdx.x;
    if (i < NC4) {
        int c4 = i % (CC / 4);
        float4 b4 = *(const float4*)&bias[c4 * 4];
        *(float4*)&out[(size_t)i * 4] = b4;
    }
    if (i < GG * (CC / 4))
        *(float4*)&outg[(size_t)i * 4] = make_float4(0.f, 0.f, 0.f, 0.f);
    if (i < NN * HH) { g_mu[i] = 0u; g_z[i] = 0.f; }
    if (i < NN) g_agg[i] = 0.f;
    if (i < GG) {
        g_gsum[i] = 0.f; g_gsq[i] = 0.f; g_gcnt[i] = 0.f;
        g_gmu[i] = 0u; g_gz[i] = 0.f;
    }
}

// per-node sums for graph-mode LayerNorm (one warp per node, float4)
__global__ void k_ln_stats(const float* __restrict__ x,
                           const int* __restrict__ batch) {
    int gw = (blockIdx.x * blockDim.x + threadIdx.x) >> 5;
    int lane = threadIdx.x & 31;
    if (gw >= NN) return;
    const float* row = &x[(size_t)gw * CC];
    float s = 0.f, s2 = 0.f;
#pragma unroll
    for (int t = 0; t < 2; t++) {
        int c4 = lane + t * 32;
        if (c4 < CC / 4) {
            float4 v = *(const float4*)&row[c4 * 4];
            s += v.x + v.y + v.z + v.w;
            s2 += v.x * v.x + v.y * v.y + v.z * v.z + v.w * v.w;
        }
    }
    s = warpSum(s); s2 = warpSum(s2);
    if (lane == 0) {
        int b = batch[gw];
        atomicAdd(&g_gsum[b], s);
        atomicAdd(&g_gsq[b], s2);
        atomicAdd(&g_gcnt[b], 1.f);
    }
}

__global__ void k_ln_final() {
    int i = blockIdx.x * blockDim.x + threadIdx.x;
    if (i >= GG) return;
    float cnt = g_gcnt[i];
    float mean = 0.f, inv = 0.f;
    if (cnt > 0.f) {
        float denom = cnt * (float)CC;
        mean = g_gsum[i] / denom;
        float var = g_gsq[i] / denom - mean * mean;
        inv = rsqrtf(var + 1e-5f);
    }
    g_gmean[i] = mean;
    g_ginv[i] = inv;
}

// h = elu(LN(x))  (float4 per thread)
__global__ void k_h(const float* __restrict__ x, const int* __restrict__ batch,
                    const float* __restrict__ lnw, const float* __restrict__ lnb) {
    int i = blockIdx.x * blockDim.x + threadIdx.x;
    if (i >= NC4) return;
    int n = i / (CC / 4);
    int c = (i - n * (CC / 4)) * 4;
    int b = batch[n];
    float mean = g_gmean[b], inv = g_ginv[b];
    float4 xv = *(const float4*)&x[(size_t)n * CC + c];
    float4 wv = *(const float4*)&lnw[c];
    float4 bv = *(const float4*)&lnb[c];
    float4 r;
    r.x = (xv.x - mean) * inv * wv.x + bv.x;
    r.y = (xv.y - mean) * inv * wv.y + bv.y;
    r.z = (xv.z - mean) * inv * wv.z + bv.z;
    r.w = (xv.w - mean) * inv * wv.w + bv.w;
    r.x = r.x > 0.f ? r.x : expm1f(r.x);
    r.y = r.y > 0.f ? r.y : expm1f(r.y);
    r.z = r.z > 0.f ? r.z : expm1f(r.z);
    r.w = r.w > 0.f ? r.w : expm1f(r.w);
    *(float4*)&g_h[(size_t)n * CC + c] = r;
}

// xh = g_h @ W  (f32x2 packed FMA; BM=128, BN=64, BK=8; 256 thr, 8x4/thread)
__global__ void __launch_bounds__(256) k_gemm(const float* __restrict__ W) {
    __shared__ __align__(16) float As[8][132];   // As[k][m], padded
    __shared__ __align__(16) float Bs[8][64];
    const int bm = blockIdx.x * 128;
    const int bn = blockIdx.y * 64;
    const int tid = threadIdx.x;
    const int tx = tid & 15;       // col group of 4
    const int ty = tid >> 4;       // row group of 8

    unsigned long long acc[4][4];  // row-pair i (rows 2i,2i+1), col j
#pragma unroll
    for (int i = 0; i < 4; i++)
#pragma unroll
        for (int j = 0; j < 4; j++) acc[i][j] = 0ull;

    const int arow = tid >> 1;           // 0..127
    const int ak0 = (tid & 1) * 4;       // 0 or 4
    const int bk = tid >> 5;             // 0..7
    const int bc0 = (tid & 31) * 2;      // 0..62

    for (int k0 = 0; k0 < CC; k0 += 8) {
        int grow = bm + arow;
        float4 av = make_float4(0.f, 0.f, 0.f, 0.f);
        if (grow < NN) av = *(const float4*)&g_h[(size_t)grow * CC + k0 + ak0];
        As[ak0 + 0][arow] = av.x;
        As[ak0 + 1][arow] = av.y;
        As[ak0 + 2][arow] = av.z;
        As[ak0 + 3][arow] = av.w;

        float2 bv = make_float2(0.f, 0.f);
        int gcol = bn + bc0;
        if (gcol < CC) bv = *(const float2*)&W[(size_t)(k0 + bk) * CC + gcol];
        Bs[bk][bc0] = bv.x;
        Bs[bk][bc0 + 1] = bv.y;
        __syncthreads();

#pragma unroll
        for (int k = 0; k < 8; k++) {
            unsigned long long a2[4];
#pragma unroll
            for (int i = 0; i < 4; i++)
                a2[i] = *(const unsigned long long*)&As[k][ty * 8 + 2 * i];
            float4 b4 = *(const float4*)&Bs[k][tx * 4];
            unsigned long long b2[4];
            b2[0] = pack2(b4.x, b4.x);
            b2[1] = pack2(b4.y, b4.y);
            b2[2] = pack2(b4.z, b4.z);
            b2[3] = pack2(b4.w, b4.w);
#pragma unroll
            for (int i = 0; i < 4; i++)
#pragma unroll
                for (int j = 0; j < 4; j++) fma2(acc[i][j], a2[i], b2[j]);
        }
        __syncthreads();
    }

#pragma unroll
    for (int i = 0; i < 4; i++) {
        int r0 = bm + ty * 8 + 2 * i;
        if (r0 >= NN) break;
        int c = bn + tx * 4;
        if (c >= CC) continue;
        float2 v0 = unpack2(acc[i][0]);
        float2 v1 = unpack2(acc[i][1]);
        float2 v2 = unpack2(acc[i][2]);
        float2 v3 = unpack2(acc[i][3]);
        *(float4*)&g_xh[(size_t)r0 * CC + c] = make_float4(v0.x, v1.x, v2.x, v3.x);
        if (r0 + 1 < NN)
            *(float4*)&g_xh[(size_t)(r0 + 1) * CC + c] = make_float4(v0.y, v1.y, v2.y, v3.y);
    }
}

// per-node attention logits (one warp per node)
__global__ void k_att(const float* __restrict__ att_s, const float* __restrict__ att_d) {
    __shared__ float s_as[CC], s_ad[CC];
    for (int i = threadIdx.x; i < CC; i += blockDim.x) {
        s_as[i] = att_s[i];
        s_ad[i] = att_d[i];
    }
    __syncthreads();
    int gw = (blockIdx.x * blockDim.x + threadIdx.x) >> 5;
    int lane = threadIdx.x & 31;
    if (gw >= NN) return;
    const float* row = &g_xh[(size_t)gw * CC];
#pragma unroll
    for (int hh = 0; hh < HH; hh++) {
        float ss = 0.f, sd = 0.f;
#pragma unroll
        for (int t = 0; t < 2; t++) {
            int d = lane + t * 32;
            if (d < DD) {
                float v = row[hh * DD + d];
                ss += v * s_as[hh * DD + d];
                sd += v * s_ad[hh * DD + d];
            }
        }
        ss = warpSum(ss); sd = warpSum(sd);
        if (lane == 0) {
            g_asrc[gw * HH + hh] = ss;
            g_adst[gw * HH + hh] = sd;
        }
    }
}

__device__ __forceinline__ void edge_ends(const int* ei, int i, int& src, int& dst) {
    if (i < EE) { src = ei[i]; dst = ei[EE + i]; }
    else        { src = i - EE; dst = src; }
}

__global__ void k_edge_max(const int* __restrict__ ei) {
    int i = blockIdx.x * blockDim.x + threadIdx.x;
    if (i >= EN) return;
    int src, dst;
    edge_ends(ei, i, src, dst);
    float4 as = *(const float4*)&g_asrc[src * 4];
    float4 ad = *(const float4*)&g_adst[dst * 4];
    atomicMax(&g_mu[dst * 4 + 0], fkey(lrelu(as.x + ad.x)));
    atomicMax(&g_mu[dst * 4 + 1], fkey(lrelu(as.y + ad.y)));
    atomicMax(&g_mu[dst * 4 + 2], fkey(lrelu(as.z + ad.z)));
    atomicMax(&g_mu[dst * 4 + 3], fkey(lrelu(as.w + ad.w)));
}

__global__ void k_edge_exp(const int* __restrict__ ei) {
    int i = blockIdx.x * blockDim.x + threadIdx.x;
    if (i >= EN) return;
    int src, dst;
    edge_ends(ei, i, src, dst);
    float4 as = *(const float4*)&g_asrc[src * 4];
    float4 ad = *(const float4*)&g_adst[dst * 4];
    float e0 = expf(lrelu(as.x + ad.x) - funkey(g_mu[dst * 4 + 0]));
    float e1 = expf(lrelu(as.y + ad.y) - funkey(g_mu[dst * 4 + 1]));
    float e2 = expf(lrelu(as.z + ad.z) - funkey(g_mu[dst * 4 + 2]));
    float e3 = expf(lrelu(as.w + ad.w) - funkey(g_mu[dst * 4 + 3]));
    *(float4*)&g_e[(size_t)i * 4] = make_float4(e0, e1, e2, e3);
    red_add_v4(&g_z[dst * 4], e0, e1, e2, e3);
}

// out[dst] += xh[src] * att  (one warp per edge; float4 gather + v4 reduction)
__global__ void k_edge_scatter(const int* __restrict__ ei, float* __restrict__ out) {
    int gw = (blockIdx.x * blockDim.x + threadIdx.x) >> 5;
    int lane = threadIdx.x & 31;
    if (gw >= EN) return;
    int src, dst;
    edge_ends(ei, gw, src, dst);
    float4 ev = *(const float4*)&g_e[(size_t)gw * 4];
    float4 zv = *(const float4*)&g_z[dst * 4];
    float att[HH];
    att[0] = ev.x / (zv.x + 1e-16f);
    att[1] = ev.y / (zv.y + 1e-16f);
    att[2] = ev.z / (zv.z + 1e-16f);
    att[3] = ev.w / (zv.w + 1e-16f);
    const float* xr = &g_xh[(size_t)src * CC];
    float* orow = &out[(size_t)dst * CC];
#pragma unroll
    for (int t = 0; t < 2; t++) {
        int c4 = lane + t * 32;
        if (c4 < CC / 4) {
            int c = c4 * 4;
            float4 xv = *(const float4*)&xr[c];
            float a0 = att[(c + 0) / DD];
            float a1 = att[(c + 1) / DD];
            float a2 = att[(c + 2) / DD];
            float a3 = att[(c + 3) / DD];
            red_add_v4(&orow[c], xv.x * a0, xv.y * a1, xv.z * a2, xv.w * a3);
        }
    }
}

// per-node projections: srel = out . w_rel ; sbase = out . w_root + b_rel
__global__ void k_score_node(const float* __restrict__ out, const float* __restrict__ w_rel,
                             const float* __restrict__ w_root, const float* __restrict__ b_rel) {
    int gw = (blockIdx.x * blockDim.x + threadIdx.x) >> 5;
    int lane = threadIdx.x & 31;
    if (gw >= NN) return;
    const float* r = &out[(size_t)gw * CC];
    float sr = 0.f, sb = 0.f;
#pragma unroll
    for (int t = 0; t < 2; t++) {
        int c4 = lane + t * 32;
        if (c4 < CC / 4) {
            int c = c4 * 4;
            float4 v = *(const float4*)&r[c];
            float4 wr = *(const float4*)&w_rel[c];
            float4 wo = *(const float4*)&w_root[c];
            sr += v.x * wr.x + v.y * wr.y + v.z * wr.z + v.w * wr.w;
            sb += v.x * wo.x + v.y * wo.y + v.z * wo.z + v.w * wo.w;
        }
    }
    sr = warpSum(sr); sb = warpSum(sb);
    if (lane == 0) {
        g_srel[gw] = sr;
        g_sbase[gw] = sb + b_rel[0];
    }
}

__global__ void k_edge_rel(const int* __restrict__ ei) {
    int i = blockIdx.x * blockDim.x + threadIdx.x;
    if (i >= EE) return;
    atomicAdd(&g_agg[ei[EE + i]], g_srel[ei[i]]);
}

__global__ void k_score_max(const int* __restrict__ batch) {
    int i = blockIdx.x * blockDim.x + threadIdx.x;
    if (i >= NN) return;
    float s = g_agg[i] + g_sbase[i];
    g_sbase[i] = s;
    atomicMax(&g_gmu[batch[i]], fkey(s));
}

__global__ void k_score_exp(const int* __restrict__ batch) {
    int i = blockIdx.x * blockDim.x + threadIdx.x;
    if (i >= NN) return;
    int b = batch[i];
    float es = expf(g_sbase[i] - funkey(g_gmu[b]));
    g_es[i] = es;
    atomicAdd(&g_gz[b], es);
}

__global__ void k_scale(const int* __restrict__ batch) {
    int i = blockIdx.x * blockDim.x + threadIdx.x;
    if (i >= NN) return;
    g_scale[i] = g_es[i] / g_gz[batch[i]];
}

// xp = out*scale (in place, float4) ; outg[batch] += xp (v4 reduction)
__global__ void k_finalize(float* __restrict__ out, float* __restrict__ outg,
                           const int* __restrict__ batch) {
    int i = blockIdx.x * blockDim.x + threadIdx.x;
    if (i >= NC4) return;
    int n = i / (CC / 4);
    int c = (i - n * (CC / 4)) * 4;
    float sc = g_scale[n];
    float4 v = *(const float4*)&out[(size_t)n * CC + c];
    v.x *= sc; v.y *= sc; v.z *= sc; v.w *= sc;
    *(float4*)&out[(size_t)n * CC + c] = v;
    red_add_v4(&outg[(size_t)batch[n] * CC + c], v.x, v.y, v.z, v.w);
}

// ---------------- launch ----------------------------------------------------
extern "C" void kernel_launch(void* const* d_in, const int* in_sizes, int n_in,
                              void* d_out, int out_size) {
    const float* x = (const float*)d_in[0];
    const int* ei = (const int*)d_in[1];
    const int* batch = (const int*)d_in[2];
    const float* ln_w = (const float*)d_in[3];
    const float* ln_b = (const float*)d_in[4];
    const float* W_gat = (const float*)d_in[5];
    const float* att_s = (const float*)d_in[6];
    const float* att_d = (const float*)d_in[7];
    const float* bias = (const float*)d_in[8];
    const float* w_rel = (const float*)d_in[9];
    const float* b_rel = (const float*)d_in[10];
    const float* w_root = (const float*)d_in[11];

    float* out = (float*)d_out;                 // xp region [N, C]
    float* outg = out + (size_t)NN * CC;        // g region  [G, C]

    const int T = 256;
    const int blocksV4 = (NC4 + T - 1) / T;           // 19532
    const int warpNodeBlocks = (NN + 7) / 8;          // 12500
    const int edgeBlocks = (EN + T - 1) / T;          // 1954
    const int edgeWarpBlocks = (EN + 7) / 8;          // 62500
    const int nodeBlocks = (NN + T - 1) / T;          // 391
    (void)in_sizes; (void)n_in; (void)out_size;

    k_init<<<blocksV4, T>>>(out, outg, bias);
    k_ln_stats<<<warpNodeBlocks, T>>>(x, batch);
    k_ln_final<<<(GG + T - 1) / T, T>>>();
    k_h<<<blocksV4, T>>>(x, batch, ln_w, ln_b);

    dim3 gemmGrid((NN + 127) / 128, 4);
    k_gemm<<<gemmGrid, 256>>>(W_gat);

    k_att<<<warpNodeBlocks, T>>>(att_s, att_d);
    k_edge_max<<<edgeBlocks, T>>>(ei);
    k_edge_exp<<<edgeBlocks, T>>>(ei);
    k_edge_scatter<<<edgeWarpBlocks, T>>>(ei, out);

    k_score_node<<<warpNodeBlocks, T>>>(out, w_rel, w_root, b_rel);
    k_edge_rel<<<(EE + T - 1) / T, T>>>(ei);
    k_score_max<<<nodeBlocks, T>>>(batch);
    k_score_exp<<<nodeBlocks, T>>>(batch);
    k_scale<<<nodeBlocks, T>>>(batch);
    k_finalize<<<blocksV4, T>>>(out, outg, batch);
}

// round 6
// speedup vs baseline: 1.4136x; 1.1244x over previous
#include <cuda_runtime.h>
#include <cfloat>

#define NN 100000
#define CC 200
#define EE 400000
#define GG 512
#define HH 4
#define DD 50
#define NC4 (NN * (CC / 4))
#define SCAN_B 1024
#define SCAN_NB ((NN + SCAN_B - 1) / SCAN_B)   // 98

// ---------------- scratch ----------------------------------------------------
__device__ __align__(16) float g_h[(size_t)NN * CC];
__device__ __align__(16) float g_xh[(size_t)NN * CC];
__device__ __align__(16) float g_asrc[NN * HH];
__device__ __align__(16) float g_adst[NN * HH];
__device__ float g_gsum[GG], g_gsq[GG], g_gcnt[GG], g_gmean[GG], g_ginv[GG];
__device__ float g_srel[NN], g_sbase[NN], g_es[NN], g_scale[NN];
__device__ unsigned g_gmu[GG];
__device__ float g_gz[GG];
// CSR
__device__ int g_cnt[NN];       // in-degree (original edges)
__device__ int g_base[NN];      // exclusive scan of cnt
__device__ int g_cursor[NN];
__device__ int g_csrc[EE];      // sources grouped by dst
__device__ int g_bsum[SCAN_NB];
__device__ int g_bsumx[SCAN_NB];

// ---------------- helpers ---------------------------------------------------
__device__ __forceinline__ unsigned fkey(float f) {
    unsigned b = __float_as_uint(f);
    return b ^ ((unsigned)((int)b >> 31) | 0x80000000u);
}
__device__ __forceinline__ float funkey(unsigned u) {
    unsigned b = (u & 0x80000000u) ? (u ^ 0x80000000u) : ~u;
    return __uint_as_float(b);
}
__device__ __forceinline__ float warpSum(float v) {
#pragma unroll
    for (int o = 16; o; o >>= 1) v += __shfl_xor_sync(0xffffffffu, v, o);
    return v;
}
__device__ __forceinline__ float warpMax(float v) {
#pragma unroll
    for (int o = 16; o; o >>= 1) v = fmaxf(v, __shfl_xor_sync(0xffffffffu, v, o));
    return v;
}
__device__ __forceinline__ float lrelu(float a) { return a > 0.f ? a : 0.2f * a; }

__device__ __forceinline__ unsigned long long pack2(float x, float y) {
    unsigned long long r;
    asm("mov.b64 %0, {%1, %2};" : "=l"(r)
        : "r"(__float_as_uint(x)), "r"(__float_as_uint(y)));
    return r;
}
__device__ __forceinline__ void fma2(unsigned long long& d, unsigned long long a,
                                     unsigned long long b) {
    asm("fma.rn.f32x2 %0, %1, %2, %0;" : "+l"(d) : "l"(a), "l"(b));
}
__device__ __forceinline__ float2 unpack2(unsigned long long v) {
    unsigned lo, hi;
    asm("mov.b64 {%0, %1}, %2;" : "=r"(lo), "=r"(hi) : "l"(v));
    return make_float2(__uint_as_float(lo), __uint_as_float(hi));
}
__device__ __forceinline__ void red_add_v4(float* addr, float a, float b, float c, float d) {
    asm volatile("red.global.add.v4.f32 [%0], {%1, %2, %3, %4};"
                 :: "l"(addr), "f"(a), "f"(b), "f"(c), "f"(d) : "memory");
}

// ---------------- kernels ----------------------------------------------------

__global__ void k_init(float* __restrict__ outg) {
    int i = blockIdx.x * blockDim.x + threadIdx.x;
    if (i < NN) g_cnt[i] = 0;
    if (i < GG * (CC / 4))
        *(float4*)&outg[(size_t)i * 4] = make_float4(0.f, 0.f, 0.f, 0.f);
    if (i < GG) {
        g_gsum[i] = 0.f; g_gsq[i] = 0.f; g_gcnt[i] = 0.f;
        g_gmu[i] = 0u; g_gz[i] = 0.f;
    }
}

__global__ void k_ln_stats(const float* __restrict__ x,
                           const int* __restrict__ batch) {
    int gw = (blockIdx.x * blockDim.x + threadIdx.x) >> 5;
    int lane = threadIdx.x & 31;
    if (gw >= NN) return;
    const float* row = &x[(size_t)gw * CC];
    float s = 0.f, s2 = 0.f;
#pragma unroll
    for (int t = 0; t < 2; t++) {
        int c4 = lane + t * 32;
        if (c4 < CC / 4) {
            float4 v = *(const float4*)&row[c4 * 4];
            s += v.x + v.y + v.z + v.w;
            s2 += v.x * v.x + v.y * v.y + v.z * v.z + v.w * v.w;
        }
    }
    s = warpSum(s); s2 = warpSum(s2);
    if (lane == 0) {
        int b = batch[gw];
        atomicAdd(&g_gsum[b], s);
        atomicAdd(&g_gsq[b], s2);
        atomicAdd(&g_gcnt[b], 1.f);
    }
}

__global__ void k_ln_final() {
    int i = blockIdx.x * blockDim.x + threadIdx.x;
    if (i >= GG) return;
    float cnt = g_gcnt[i];
    float mean = 0.f, inv = 0.f;
    if (cnt > 0.f) {
        float denom = cnt * (float)CC;
        mean = g_gsum[i] / denom;
        float var = g_gsq[i] / denom - mean * mean;
        inv = rsqrtf(var + 1e-5f);
    }
    g_gmean[i] = mean;
    g_ginv[i] = inv;
}

__global__ void k_h(const float* __restrict__ x, const int* __restrict__ batch,
                    const float* __restrict__ lnw, const float* __restrict__ lnb) {
    int i = blockIdx.x * blockDim.x + threadIdx.x;
    if (i >= NC4) return;
    int n = i / (CC / 4);
    int c = (i - n * (CC / 4)) * 4;
    int b = batch[n];
    float mean = g_gmean[b], inv = g_ginv[b];
    float4 xv = *(const float4*)&x[(size_t)n * CC + c];
    float4 wv = *(const float4*)&lnw[c];
    float4 bv = *(const float4*)&lnb[c];
    float4 r;
    r.x = (xv.x - mean) * inv * wv.x + bv.x;
    r.y = (xv.y - mean) * inv * wv.y + bv.y;
    r.z = (xv.z - mean) * inv * wv.z + bv.z;
    r.w = (xv.w - mean) * inv * wv.w + bv.w;
    r.x = r.x > 0.f ? r.x : (__expf(r.x) - 1.f);
    r.y = r.y > 0.f ? r.y : (__expf(r.y) - 1.f);
    r.z = r.z > 0.f ? r.z : (__expf(r.z) - 1.f);
    r.w = r.w > 0.f ? r.w : (__expf(r.w) - 1.f);
    *(float4*)&g_h[(size_t)n * CC + c] = r;
}

// xh = g_h @ W ; grid.x = col-blocks (4) so same A-tile blocks run concurrently
__global__ void __launch_bounds__(256) k_gemm(const float* __restrict__ W) {
    __shared__ __align__(16) float As[8][132];
    __shared__ __align__(16) float Bs[8][64];
    const int bm = blockIdx.y * 128;
    const int bn = blockIdx.x * 64;
    const int tid = threadIdx.x;
    const int tx = tid & 15;
    const int ty = tid >> 4;

    unsigned long long acc[4][4];
#pragma unroll
    for (int i = 0; i < 4; i++)
#pragma unroll
        for (int j = 0; j < 4; j++) acc[i][j] = 0ull;

    const int arow = tid >> 1;
    const int ak0 = (tid & 1) * 4;
    const int bk = tid >> 5;
    const int bc0 = (tid & 31) * 2;

    for (int k0 = 0; k0 < CC; k0 += 8) {
        int grow = bm + arow;
        float4 av = make_float4(0.f, 0.f, 0.f, 0.f);
        if (grow < NN) av = *(const float4*)&g_h[(size_t)grow * CC + k0 + ak0];
        As[ak0 + 0][arow] = av.x;
        As[ak0 + 1][arow] = av.y;
        As[ak0 + 2][arow] = av.z;
        As[ak0 + 3][arow] = av.w;

        float2 bv = make_float2(0.f, 0.f);
        int gcol = bn + bc0;
        if (gcol < CC) bv = *(const float2*)&W[(size_t)(k0 + bk) * CC + gcol];
        Bs[bk][bc0] = bv.x;
        Bs[bk][bc0 + 1] = bv.y;
        __syncthreads();

#pragma unroll
        for (int k = 0; k < 8; k++) {
            unsigned long long a2[4];
#pragma unroll
            for (int i = 0; i < 4; i++)
                a2[i] = *(const unsigned long long*)&As[k][ty * 8 + 2 * i];
            float4 b4 = *(const float4*)&Bs[k][tx * 4];
            unsigned long long b2[4];
            b2[0] = pack2(b4.x, b4.x);
            b2[1] = pack2(b4.y, b4.y);
            b2[2] = pack2(b4.z, b4.z);
            b2[3] = pack2(b4.w, b4.w);
#pragma unroll
            for (int i = 0; i < 4; i++)
#pragma unroll
                for (int j = 0; j < 4; j++) fma2(acc[i][j], a2[i], b2[j]);
        }
        __syncthreads();
    }

#pragma unroll
    for (int i = 0; i < 4; i++) {
        int r0 = bm + ty * 8 + 2 * i;
        if (r0 >= NN) break;
        int c = bn + tx * 4;
        if (c >= CC) continue;
        float2 v0 = unpack2(acc[i][0]);
        float2 v1 = unpack2(acc[i][1]);
        float2 v2 = unpack2(acc[i][2]);
        float2 v3 = unpack2(acc[i][3]);
        *(float4*)&g_xh[(size_t)r0 * CC + c] = make_float4(v0.x, v1.x, v2.x, v3.x);
        if (r0 + 1 < NN)
            *(float4*)&g_xh[(size_t)(r0 + 1) * CC + c] = make_float4(v0.y, v1.y, v2.y, v3.y);
    }
}

__global__ void k_att(const float* __restrict__ att_s, const float* __restrict__ att_d) {
    __shared__ float s_as[CC], s_ad[CC];
    for (int i = threadIdx.x; i < CC; i += blockDim.x) {
        s_as[i] = att_s[i];
        s_ad[i] = att_d[i];
    }
    __syncthreads();
    int gw = (blockIdx.x * blockDim.x + threadIdx.x) >> 5;
    int lane = threadIdx.x & 31;
    if (gw >= NN) return;
    const float* row = &g_xh[(size_t)gw * CC];
#pragma unroll
    for (int hh = 0; hh < HH; hh++) {
        float ss = 0.f, sd = 0.f;
#pragma unroll
        for (int t = 0; t < 2; t++) {
            int d = lane + t * 32;
            if (d < DD) {
                float v = row[hh * DD + d];
                ss += v * s_as[hh * DD + d];
                sd += v * s_ad[hh * DD + d];
            }
        }
        ss = warpSum(ss); sd = warpSum(sd);
        if (lane == 0) {
            g_asrc[gw * HH + hh] = ss;
            g_adst[gw * HH + hh] = sd;
        }
    }
}

// ---- CSR build ----
__global__ void k_count(const int* __restrict__ ei) {
    int i = blockIdx.x * blockDim.x + threadIdx.x;
    if (i >= EE) return;
    atomicAdd(&g_cnt[ei[EE + i]], 1);
}

__global__ void k_scan_block() {
    __shared__ int sm[SCAN_B];
    int i = blockIdx.x * SCAN_B + threadIdx.x;
    int v = (i < NN) ? g_cnt[i] : 0;
    sm[threadIdx.x] = v;
    __syncthreads();
    // Hillis-Steele inclusive scan
    for (int o = 1; o < SCAN_B; o <<= 1) {
        int t = (threadIdx.x >= o) ? sm[threadIdx.x - o] : 0;
        __syncthreads();
        sm[threadIdx.x] += t;
        __syncthreads();
    }
    if (i < NN) g_base[i] = sm[threadIdx.x] - v;   // exclusive
    if (threadIdx.x == SCAN_B - 1) g_bsum[blockIdx.x] = sm[threadIdx.x];
}

__global__ void k_scan_top() {
    if (threadIdx.x == 0) {
        int run = 0;
        for (int b = 0; b < SCAN_NB; b++) {
            g_bsumx[b] = run;
            run += g_bsum[b];
        }
    }
}

__global__ void k_scan_add() {
    int i = blockIdx.x * blockDim.x + threadIdx.x;
    if (i >= NN) return;
    int v = g_base[i] + g_bsumx[i / SCAN_B];
    g_base[i] = v;
    g_cursor[i] = v;
}

__global__ void k_fill(const int* __restrict__ ei) {
    int i = blockIdx.x * blockDim.x + threadIdx.x;
    if (i >= EE) return;
    int dst = ei[EE + i];
    int pos = atomicAdd(&g_cursor[dst], 1);
    g_csrc[pos] = ei[i];
}

// ---- GAT softmax + aggregation, one warp per dst node ----
__global__ void __launch_bounds__(256) k_gat(float* __restrict__ out,
                                             const float* __restrict__ bias) {
    __shared__ float s_e[8][32][4];
    __shared__ int s_src[8][32];
    int w = threadIdx.x >> 5;
    int lane = threadIdx.x & 31;
    int n = blockIdx.x * 8 + w;
    if (n >= NN) return;
    int base = g_base[n];
    int deg = g_cnt[n];

    float4 ad = *(const float4*)&g_adst[n * 4];
    float4 asn = *(const float4*)&g_asrc[n * 4];
    float sf0 = lrelu(asn.x + ad.x), sf1 = lrelu(asn.y + ad.y);
    float sf2 = lrelu(asn.z + ad.z), sf3 = lrelu(asn.w + ad.w);

    // pass 1: max per head (self alpha is the init)
    float m0 = sf0, m1 = sf1, m2 = sf2, m3 = sf3;
    for (int j = lane; j < deg; j += 32) {
        int src = g_csrc[base + j];
        float4 as = *(const float4*)&g_asrc[src * 4];
        m0 = fmaxf(m0, lrelu(as.x + ad.x));
        m1 = fmaxf(m1, lrelu(as.y + ad.y));
        m2 = fmaxf(m2, lrelu(as.z + ad.z));
        m3 = fmaxf(m3, lrelu(as.w + ad.w));
    }
    m0 = warpMax(m0); m1 = warpMax(m1); m2 = warpMax(m2); m3 = warpMax(m3);

    // pass 2: chunked exp + accumulation (unnormalized)
    float acc[7];
#pragma unroll
    for (int t = 0; t < 7; t++) acc[t] = 0.f;
    float z0 = 0.f, z1 = 0.f, z2 = 0.f, z3 = 0.f;

    for (int c0 = 0; c0 < deg; c0 += 32) {
        int j = c0 + lane;
        int cn = min(32, deg - c0);
        if (j < deg) {
            int src = g_csrc[base + j];
            s_src[w][lane] = src;
            float4 as = *(const float4*)&g_asrc[src * 4];
            float e0 = __expf(lrelu(as.x + ad.x) - m0);
            float e1 = __expf(lrelu(as.y + ad.y) - m1);
            float e2 = __expf(lrelu(as.z + ad.z) - m2);
            float e3 = __expf(lrelu(as.w + ad.w) - m3);
            s_e[w][lane][0] = e0; s_e[w][lane][1] = e1;
            s_e[w][lane][2] = e2; s_e[w][lane][3] = e3;
            z0 += e0; z1 += e1; z2 += e2; z3 += e3;
        }
        __syncwarp();
        for (int jj = 0; jj < cn; jj++) {
            int src = s_src[w][jj];
            float e0 = s_e[w][jj][0], e1 = s_e[w][jj][1];
            float e2 = s_e[w][jj][2], e3 = s_e[w][jj][3];
            const float* xr = &g_xh[(size_t)src * CC];
#pragma unroll
            for (int t = 0; t < 7; t++) {
                int c = lane + t * 32;
                if (c < CC) {
                    int hh = c / DD;
                    float e = hh == 0 ? e0 : hh == 1 ? e1 : hh == 2 ? e2 : e3;
                    acc[t] += xr[c] * e;
                }
            }
        }
        __syncwarp();
    }
    z0 = warpSum(z0); z1 = warpSum(z1); z2 = warpSum(z2); z3 = warpSum(z3);

    // self loop
    float es0 = __expf(sf0 - m0), es1 = __expf(sf1 - m1);
    float es2 = __expf(sf2 - m2), es3 = __expf(sf3 - m3);
    z0 += es0; z1 += es1; z2 += es2; z3 += es3;
    z0 += 1e-16f; z1 += 1e-16f; z2 += 1e-16f; z3 += 1e-16f;
    const float* xn = &g_xh[(size_t)n * CC];
    float* orow = &out[(size_t)n * CC];
#pragma unroll
    for (int t = 0; t < 7; t++) {
        int c = lane + t * 32;
        if (c < CC) {
            int hh = c / DD;
            float es = hh == 0 ? es0 : hh == 1 ? es1 : hh == 2 ? es2 : es3;
            float z = hh == 0 ? z0 : hh == 1 ? z1 : hh == 2 ? z2 : z3;
            orow[c] = (acc[t] + xn[c] * es) / z + bias[c];
        }
    }
}

__global__ void k_score_node(const float* __restrict__ out, const float* __restrict__ w_rel,
                             const float* __restrict__ w_root, const float* __restrict__ b_rel) {
    int gw = (blockIdx.x * blockDim.x + threadIdx.x) >> 5;
    int lane = threadIdx.x & 31;
    if (gw >= NN) return;
    const float* r = &out[(size_t)gw * CC];
    float sr = 0.f, sb = 0.f;
#pragma unroll
    for (int t = 0; t < 2; t++) {
        int c4 = lane + t * 32;
        if (c4 < CC / 4) {
            int c = c4 * 4;
            float4 v = *(const float4*)&r[c];
            float4 wr = *(const float4*)&w_rel[c];
            float4 wo = *(const float4*)&w_root[c];
            sr += v.x * wr.x + v.y * wr.y + v.z * wr.z + v.w * wr.w;
            sb += v.x * wo.x + v.y * wo.y + v.z * wo.z + v.w * wo.w;
        }
    }
    sr = warpSum(sr); sb = warpSum(sb);
    if (lane == 0) {
        g_srel[gw] = sr;
        g_sbase[gw] = sb + b_rel[0];
    }
}

// agg via CSR + per-graph max (thread per node)
__global__ void k_score_agg(const int* __restrict__ batch) {
    int i = blockIdx.x * blockDim.x + threadIdx.x;
    if (i >= NN) return;
    int base = g_base[i], deg = g_cnt[i];
    float s = 0.f;
    for (int j = 0; j < deg; j++) s += g_srel[g_csrc[base + j]];
    s += g_sbase[i];
    g_sbase[i] = s;
    atomicMax(&g_gmu[batch[i]], fkey(s));
}

__global__ void k_score_exp(const int* __restrict__ batch) {
    int i = blockIdx.x * blockDim.x + threadIdx.x;
    if (i >= NN) return;
    int b = batch[i];
    float es = expf(g_sbase[i] - funkey(g_gmu[b]));
    g_es[i] = es;
    atomicAdd(&g_gz[b], es);
}

__global__ void k_scale(const int* __restrict__ batch) {
    int i = blockIdx.x * blockDim.x + threadIdx.x;
    if (i >= NN) return;
    g_scale[i] = g_es[i] / g_gz[batch[i]];
}

__global__ void k_finalize(float* __restrict__ out, float* __restrict__ outg,
                           const int* __restrict__ batch) {
    int i = blockIdx.x * blockDim.x + threadIdx.x;
    if (i >= NC4) return;
    int n = i / (CC / 4);
    int c = (i - n * (CC / 4)) * 4;
    float sc = g_scale[n];
    float4 v = *(const float4*)&out[(size_t)n * CC + c];
    v.x *= sc; v.y *= sc; v.z *= sc; v.w *= sc;
    *(float4*)&out[(size_t)n * CC + c] = v;
    red_add_v4(&outg[(size_t)batch[n] * CC + c], v.x, v.y, v.z, v.w);
}

// ---------------- launch ----------------------------------------------------
extern "C" void kernel_launch(void* const* d_in, const int* in_sizes, int n_in,
                              void* d_out, int out_size) {
    const float* x = (const float*)d_in[0];
    const int* ei = (const int*)d_in[1];
    const int* batch = (const int*)d_in[2];
    const float* ln_w = (const float*)d_in[3];
    const float* ln_b = (const float*)d_in[4];
    const float* W_gat = (const float*)d_in[5];
    const float* att_s = (const float*)d_in[6];
    const float* att_d = (const float*)d_in[7];
    const float* bias = (const float*)d_in[8];
    const float* w_rel = (const float*)d_in[9];
    const float* b_rel = (const float*)d_in[10];
    const float* w_root = (const float*)d_in[11];

    float* out = (float*)d_out;
    float* outg = out + (size_t)NN * CC;

    const int T = 256;
    const int blocksV4 = (NC4 + T - 1) / T;
    const int warpNodeBlocks = (NN + 7) / 8;
    const int nodeBlocks = (NN + T - 1) / T;
    const int edgeBlocks = (EE + T - 1) / T;
    (void)in_sizes; (void)n_in; (void)out_size;

    k_init<<<nodeBlocks, T>>>(outg);
    k_ln_stats<<<warpNodeBlocks, T>>>(x, batch);
    k_ln_final<<<(GG + T - 1) / T, T>>>();
    k_h<<<blocksV4, T>>>(x, batch, ln_w, ln_b);

    dim3 gemmGrid(4, (NN + 127) / 128);   // x = col-block (fast) -> L2 A reuse
    k_gemm<<<gemmGrid, 256>>>(W_gat);

    k_att<<<warpNodeBlocks, T>>>(att_s, att_d);

    // CSR build
    k_count<<<edgeBlocks, T>>>(ei);
    k_scan_block<<<SCAN_NB, SCAN_B>>>();
    k_scan_top<<<1, 32>>>();
    k_scan_add<<<(NN + SCAN_B - 1) / SCAN_B, SCAN_B>>>();
    k_fill<<<edgeBlocks, T>>>(ei);

    k_gat<<<warpNodeBlocks, T>>>(out, bias);

    k_score_node<<<warpNodeBlocks, T>>>(out, w_rel, w_root, b_rel);
    k_score_agg<<<nodeBlocks, T>>>(batch);
    k_score_exp<<<nodeBlocks, T>>>(batch);
    k_scale<<<nodeBlocks, T>>>(batch);
    k_finalize<<<blocksV4, T>>>(out, outg, batch);
}